// round 16
// baseline (speedup 1.0000x reference)
#include <cuda_runtime.h>
#include <cuda_fp16.h>
#include <cstdint>

// out[s,b,o,hw] = sum_k adc_real[b,k,hw]*W[s*256+o,k] + adc_imag[b,k,hw]*W[s*256+o,256+k]
// GEMM D[512, 4*65536] = W[512,512] * X[512,*] via mma.sync m16n8k16 fp16 (fp32 acc).
// R16 = R15 with the pipeline race fixed: all writes into stage 1-s (cp.async W
// fill and X STS) are issued strictly AFTER the barrier that retires chunk i-1's
// readers; cp.async.wait_group 0 drains the single pending W group per chunk.
// KC=64 (two 32-k sub-chunks per stage), NSTG=2, 8 chunk boundaries.

#define NFFT 256
#define HW   65536
#define KTOT 512
#define MT   256
#define NT   128
#define NSTG 2
#define WPH2 40                  // W row pitch in half2 per 32-k sub-block
#define XPH2 136                 // X row pitch in half2 per 32-k sub-block
#define WSUB_B (MT * WPH2 * 4)        // 40960 B
#define XSUB_B (16 * XPH2 * 4)        // 8704 B
#define STAGE_B (2 * (WSUB_B + XSUB_B))   // 99328 B

__device__ __half wprep[16 * 512 * 32];   // [32k-chunk][row][pos], fp16 RNE, permuted

static __device__ __forceinline__ uint32_t smem_u32(const void* p) {
    uint32_t a;
    asm("{ .reg .u64 t; cvta.to.shared.u64 t, %1; cvt.u32.u64 %0, t; }" : "=r"(a) : "l"(p));
    return a;
}

#define CP_ASYNC16(d, s) asm volatile("cp.async.cg.shared.global [%0], [%1], 16;" :: "r"(d), "l"(s))
#define CP_COMMIT()      asm volatile("cp.async.commit_group;" ::: "memory")
#define CP_WAIT0()       asm volatile("cp.async.wait_group 0;" ::: "memory")

#define MMA_F16(d0,d1,d2,d3, a0,a1,a2,a3, b0,b1)                               \
    asm volatile("mma.sync.aligned.m16n8k16.row.col.f32.f16.f16.f32 "          \
        "{%0,%1,%2,%3}, {%4,%5,%6,%7}, {%8,%9}, {%0,%1,%2,%3};"                \
        : "+f"(d0), "+f"(d1), "+f"(d2), "+f"(d3)                               \
        : "r"(a0), "r"(a1), "r"(a2), "r"(a3), "r"(b0), "r"(b1))

// prep (R14-proven): W -> fp16 RNE, pairs (p, p+4) adjacent per 16-k group.
__global__ void prep_w_kernel(const float* __restrict__ w) {
    const int idx = blockIdx.x * 256 + threadIdx.x;
    const int row = idx >> 9;
    const int k   = idx & 511;
    const int kk  = k & 31;
    const int grp = kk >> 4;
    const int j   = kk & 15;
    const int pr  = j >> 1;
    const int lip = j & 1;
    const int pp  = 2 * (pr & 3) + (pr >> 2);
    const int pos = grp * 16 + pp * 2 + lip;
    wprep[(((size_t)(k >> 5) * 512) + row) * 32 + pos] = __float2half_rn(w[idx]);
}

__global__ __launch_bounds__(512, 1)
void fft_hmma_kernel(const float* __restrict__ xr,
                     const float* __restrict__ xi,
                     float* __restrict__ out) {
    extern __shared__ char smem[];
    const uint32_t sm_u32 = smem_u32(smem);

    const int tid  = threadIdx.x;
    const int lane = tid & 31;
    const int wid  = tid >> 5;
    const int wr   = wid & 3;                 // M-warp: 4 x 64 = 256
    const int wc   = wid >> 2;                // N-warp: 4 x 32 = 128
    const int ty   = lane >> 2;
    const int tx   = lane & 3;

    const int c0 = blockIdx.x * NT;
    const int by = blockIdx.y;                // s-plane; o0 = by*256
    const int o0 = by * MT;
    const int b  = blockIdx.z;

    const int x_pr = tid >> 5;                // pair row 0..15 (k = 2*x_pr, +1)
    const int x_c4 = (tid & 31) * 4;
    const size_t xoff = (size_t)b * NFFT * HW + c0 + x_c4;

    const __half* wsrc0 = wprep + (size_t)o0 * 32;

    float acc[4][4][4];
    #pragma unroll
    for (int mt = 0; mt < 4; mt++)
        #pragma unroll
        for (int nt = 0; nt < 4; nt++)
            #pragma unroll
            for (int q = 0; q < 4; q++) acc[mt][nt][q] = 0.0f;

    auto w_fill = [&](int kc64, int stage) {
        #pragma unroll
        for (int sub = 0; sub < 2; sub++) {
            const __half* src = wsrc0 + (size_t)(2 * kc64 + sub) * 512 * 32;
            const uint32_t wdst = sm_u32 + stage * STAGE_B + sub * WSUB_B;
            #pragma unroll
            for (int p = 0; p < 2; p++) {      // 1024 pieces / 512 thr
                const int idx = p * 512 + tid;
                const int r = idx >> 2, j = idx & 3;
                CP_ASYNC16(wdst + r * (WPH2 * 4) + j * 16, src + r * 32 + j * 8);
            }
        }
    };
    auto x_ldg = [&](int kc64, int sub, float4& p0, float4& p1) {
        const int kglob = kc64 * 64 + sub * 32;
        const float* xsrcp = ((kglob < 256) ? xr : xi) + xoff
                           + (size_t)((kglob & 255) + 2 * x_pr) * HW;
        p0 = *(const float4*)xsrcp;
        p1 = *(const float4*)(xsrcp + HW);
    };
    auto x_sts = [&](int stage, int sub, const float4& p0, const float4& p1) {
        __half2* xd = (__half2*)(smem + stage * STAGE_B + 2 * WSUB_B + sub * XSUB_B)
                    + x_pr * XPH2 + x_c4;
        __half2 h[4];
        h[0] = __floats2half2_rn(p0.x, p1.x);
        h[1] = __floats2half2_rn(p0.y, p1.y);
        h[2] = __floats2half2_rn(p0.z, p1.z);
        h[3] = __floats2half2_rn(p0.w, p1.w);
        *(uint4*)xd = *(uint4*)h;
    };

    const int abase = (wr * 64 + ty) * WPH2 + 2 * tx;
    const int bbase = tx * XPH2 + wc * 32 + ty;

    auto compute_sub = [&](int stage, int sub) {
        const __half2* wst = (const __half2*)(smem + stage * STAGE_B + sub * WSUB_B);
        const __half2* xst = (const __half2*)(smem + stage * STAGE_B + 2 * WSUB_B + sub * XSUB_B);
        #pragma unroll
        for (int ks = 0; ks < 2; ks++) {
            uint2 aw[4][2];
            #pragma unroll
            for (int mt = 0; mt < 4; mt++) {
                const __half2* ap = wst + abase + mt * (16 * WPH2) + ks * 8;
                aw[mt][0] = *(const uint2*)ap;
                aw[mt][1] = *(const uint2*)(ap + 8 * WPH2);
            }
            uint32_t bf[4][2];
            #pragma unroll
            for (int nt = 0; nt < 4; nt++) {
                const __half2* bp = xst + bbase + ks * (8 * XPH2) + nt * 8;
                bf[nt][0] = *(const uint32_t*)bp;
                bf[nt][1] = *(const uint32_t*)(bp + 4 * XPH2);
            }
            #pragma unroll
            for (int mt = 0; mt < 4; mt++)
                #pragma unroll
                for (int nt = 0; nt < 4; nt++)
                    MMA_F16(acc[mt][nt][0], acc[mt][nt][1], acc[mt][nt][2], acc[mt][nt][3],
                            aw[mt][0].x, aw[mt][1].x, aw[mt][0].y, aw[mt][1].y,
                            bf[nt][0], bf[nt][1]);
        }
    };

    // ---- prologue: chunk 0 ----
    float4 pa0, pa1, pb0, pb1;
    w_fill(0, 0);
    CP_COMMIT();
    x_ldg(0, 0, pa0, pa1);
    x_ldg(0, 1, pb0, pb1);
    x_sts(0, 0, pa0, pa1);
    x_sts(0, 1, pb0, pb1);

    for (int i = 0; i < 8; i++) {
        const int s = i & 1;
        const int ki = i + 1;

        CP_WAIT0();              // chunk i's W fill fully landed
        __syncthreads();         // all warps done reading stage 1-s (chunk i-1);
                                 // chunk i's X stores + W fill now visible

        if (ki < 8) {
            w_fill(ki, 1 - s);   // safe: stage 1-s retired by the barrier above
            CP_COMMIT();
            x_ldg(ki, 0, pa0, pa1);
        }

        compute_sub(s, 0);

        if (ki < 8) {
            x_ldg(ki, 1, pb0, pb1);
            x_sts(1 - s, 0, pa0, pa1);
        }

        compute_sub(s, 1);

        if (ki < 8)
            x_sts(1 - s, 1, pb0, pb1);
    }

    // ---- epilogue: direct STG.64 (R9/R14-verified layout) ----
    float* outp = out + ((size_t)(by * 4 + b) * NFFT) * (size_t)HW + c0 + wc * 32;
    #pragma unroll
    for (int mt = 0; mt < 4; mt++) {
        const int r0 = wr * 64 + mt * 16 + ty;
        #pragma unroll
        for (int nt = 0; nt < 4; nt++) {
            const int col = nt * 8 + tx * 2;
            float2 v0 = make_float2(acc[mt][nt][0], acc[mt][nt][1]);
            float2 v1 = make_float2(acc[mt][nt][2], acc[mt][nt][3]);
            *(float2*)(outp + (size_t)r0 * HW + col)       = v0;
            *(float2*)(outp + (size_t)(r0 + 8) * HW + col) = v1;
        }
    }
}

extern "C" void kernel_launch(void* const* d_in, const int* in_sizes, int n_in,
                              void* d_out, int out_size) {
    const float* xr = nullptr;
    const float* xi = nullptr;
    const float* w  = nullptr;
    for (int i = 0; i < n_in; i++) {
        if (in_sizes[i] == 4 * NFFT * HW) {
            if (!xr)      xr = (const float*)d_in[i];
            else if (!xi) xi = (const float*)d_in[i];
        } else if (in_sizes[i] == KTOT * KTOT) {
            w = (const float*)d_in[i];
        }
    }
    float* out = (float*)d_out;

    prep_w_kernel<<<1024, 256>>>(w);

    const int smem_bytes = NSTG * STAGE_B;   // 198,656
    cudaFuncSetAttribute(fft_hmma_kernel, cudaFuncAttributeMaxDynamicSharedMemorySize, smem_bytes);
    dim3 grid(HW / NT, 2, 4);   // (512, 2, 4)
    fft_hmma_kernel<<<grid, 512, smem_bytes>>>(xr, xi, out);
}